// round 4
// baseline (speedup 1.0000x reference)
#include <cuda_runtime.h>
#include <cstdint>

typedef unsigned long long ull;

// ---- f32x2 packed helpers (sm_100+ PTX) ------------------------------------

__device__ __forceinline__ ull pack2(float lo, float hi) {
    ull r;
    asm("mov.b64 %0, {%1, %2};" : "=l"(r) : "f"(lo), "f"(hi));
    return r;
}

// {a.hi, b.lo} — middle pair, register re-pairing only
__device__ __forceinline__ ull midpair(ull a, ull b) {
    ull r;
    asm("{\n\t"
        ".reg .b32 alo, ahi, blo, bhi;\n\t"
        "mov.b64 {alo, ahi}, %1;\n\t"
        "mov.b64 {blo, bhi}, %2;\n\t"
        "mov.b64 %0, {ahi, blo};\n\t"
        "}"
        : "=l"(r) : "l"(a), "l"(b));
    return r;
}

// d += a * b on packed f32x2
__device__ __forceinline__ void fma2(ull& d, ull a, ull b) {
    asm("fma.rn.f32x2 %0, %1, %2, %0;" : "+l"(d) : "l"(a), "l"(b));
}

// streaming 8B store (evict-first: output is never re-read, keep L2 for input)
__device__ __forceinline__ void stcs64(float* p, ull v) {
    asm volatile("st.global.cs.b64 [%0], %1;" :: "l"(p), "l"(v) : "memory");
}

// ---- kernel -----------------------------------------------------------------

#define C_CH   64
#define H_IN   512
#define W_IN   512
#define H_OUT  510
#define W_OUT  510
#define TY     10                 // output rows per CTA tile (510 = 51*10)
#define ROWS   (TY + 2)           // input rows staged in smem (12)
#define NTHR   256

__global__ void __launch_bounds__(NTHR, 4)
dwconv3x3_smem10_kernel(const float* __restrict__ x,
                        const float* __restrict__ w,
                        float* __restrict__ out)
{
    __shared__ float s[ROWS * W_IN];   // 12*512*4 = 24576 B -> 4 CTAs/SM

    const int tid   = threadIdx.x;
    const int ytile = blockIdx.x;      // 0..50
    const int plane = blockIdx.y;      // n*C + c, 0..1023
    const int c     = plane & (C_CH - 1);
    const int iy0   = ytile * TY;      // first input row of tile

    // ---- cooperative, fully coalesced tile load (float4 streams) ----
    {
        const float4* g = reinterpret_cast<const float4*>(
            x + (size_t)plane * (H_IN * W_IN) + (size_t)iy0 * W_IN);
        float4* sv = reinterpret_cast<float4*>(s);
        const int total4 = ROWS * W_IN / 4;    // 1536 -> 6 per thread
#pragma unroll
        for (int k = tid; k < total4; k += NTHR)
            sv[k] = g[k];
    }

    // ---- weights: splat 9 taps into packed f32x2 ----
    const float* wp = w + c * 9;
    ull wv[9];
#pragma unroll
    for (int i = 0; i < 9; ++i) {
        const float wf = __ldg(wp + i);
        wv[i] = pack2(wf, wf);
    }

    __syncthreads();

    // ---- compute: thread t owns output x-pair (2t, 2t+1), rows 0..TY-1 ----
    if (tid < W_OUT / 2) {             // 255 compute threads, 1 idle
        ull acc[TY];
#pragma unroll
        for (int o = 0; o < TY; ++o) acc[o] = 0ull;

#pragma unroll
        for (int r = 0; r < ROWS; ++r) {
            const float* srow = s + r * W_IN + 2 * tid;
            const ull A = *reinterpret_cast<const ull*>(srow);      // (i0,i1)
            const ull B = *reinterpret_cast<const ull*>(srow + 2);  // (i2,i3)
            const ull M = midpair(A, B);                            // (i1,i2)

#pragma unroll
            for (int ky = 0; ky < 3; ++ky) {
                const int o = r - ky;
                if (o >= 0 && o < TY) {
                    fma2(acc[o], wv[ky * 3 + 0], A);
                    fma2(acc[o], wv[ky * 3 + 1], M);
                    fma2(acc[o], wv[ky * 3 + 2], B);
                }
            }
        }

        float* op = out + (size_t)plane * (H_OUT * W_OUT)
                        + (size_t)iy0 * W_OUT + 2 * tid;
#pragma unroll
        for (int o = 0; o < TY; ++o)
            stcs64(op + (size_t)o * W_OUT, acc[o]);
    }
}

// ---- launch -----------------------------------------------------------------

extern "C" void kernel_launch(void* const* d_in, const int* in_sizes, int n_in,
                              void* d_out, int out_size)
{
    const float* x   = (const float*)d_in[0];   // (16, 64, 512, 512) fp32
    const float* w   = (const float*)d_in[1];   // (64, 3, 3) fp32
    float*       out = (float*)d_out;           // (16, 64, 510, 510) fp32

    dim3 grid(H_OUT / TY, 16 * C_CH);           // (51, 1024)
    dim3 block(NTHR);
    dwconv3x3_smem10_kernel<<<grid, block>>>(x, w, out);
}

// round 6
// speedup vs baseline: 1.0476x; 1.0476x over previous
#include <cuda_runtime.h>
#include <cstdint>

typedef unsigned long long ull;

// ---- f32x2 packed helpers (sm_100+ PTX) ------------------------------------

__device__ __forceinline__ ull pack2(float lo, float hi) {
    ull r;
    asm("mov.b64 %0, {%1, %2};" : "=l"(r) : "f"(lo), "f"(hi));
    return r;
}

// {a.hi, b.lo} — middle pair, register re-pairing only
__device__ __forceinline__ ull midpair(ull a, ull b) {
    ull r;
    asm("{\n\t"
        ".reg .b32 alo, ahi, blo, bhi;\n\t"
        "mov.b64 {alo, ahi}, %1;\n\t"
        "mov.b64 {blo, bhi}, %2;\n\t"
        "mov.b64 %0, {ahi, blo};\n\t"
        "}"
        : "=l"(r) : "l"(a), "l"(b));
    return r;
}

// d += a * b on packed f32x2
__device__ __forceinline__ void fma2(ull& d, ull a, ull b) {
    asm("fma.rn.f32x2 %0, %1, %2, %0;" : "+l"(d) : "l"(a), "l"(b));
}

// ---- kernel -----------------------------------------------------------------

#define C_CH   64
#define H_IN   512
#define W_IN   512
#define H_OUT  510
#define W_OUT  510
#define TY     10                 // output rows per CTA tile (510 = 51*10)
#define ROWS   (TY + 2)           // input rows staged in smem (12)
#define NTHR   256

__global__ void __launch_bounds__(NTHR, 5)
dwconv3x3_cpasync_kernel(const float* __restrict__ x,
                         const float* __restrict__ w,
                         float* __restrict__ out)
{
    __shared__ float s[ROWS * W_IN];   // 12*512*4 = 24576 B

    const int tid   = threadIdx.x;
    const int ytile = blockIdx.x;      // 0..50
    const int plane = blockIdx.y;      // n*C + c, 0..1023
    const int c     = plane & (C_CH - 1);
    const int iy0   = ytile * TY;      // first input row of tile

    // ---- cooperative coalesced tile load via cp.async (no dest registers) ----
    {
        const char* gbase = reinterpret_cast<const char*>(
            x + (size_t)plane * (H_IN * W_IN) + (size_t)iy0 * W_IN);
        uint32_t sbase;
        asm("{ .reg .u64 t; cvta.to.shared.u64 t, %1; cvt.u32.u64 %0, t; }"
            : "=r"(sbase) : "l"(s));
        const int total16 = ROWS * W_IN * 4 / 16;   // 1536 chunks of 16B
#pragma unroll
        for (int k = tid; k < total16; k += NTHR) {
            asm volatile("cp.async.cg.shared.global [%0], [%1], 16;"
                         :: "r"(sbase + k * 16), "l"(gbase + (size_t)k * 16));
        }
        asm volatile("cp.async.commit_group;");
    }

    // ---- weights: splat 9 taps into packed f32x2 (overlaps with cp.async) ----
    const float* wp = w + c * 9;
    ull wv[9];
#pragma unroll
    for (int i = 0; i < 9; ++i) {
        const float wf = __ldg(wp + i);
        wv[i] = pack2(wf, wf);
    }

    asm volatile("cp.async.wait_group 0;");
    __syncthreads();

    // ---- compute: thread t owns output x-pair (2t, 2t+1), rows 0..TY-1 ----
    if (tid < W_OUT / 2) {             // 255 compute threads, 1 idle
        ull acc[TY];
#pragma unroll
        for (int o = 0; o < TY; ++o) acc[o] = 0ull;

#pragma unroll
        for (int r = 0; r < ROWS; ++r) {
            const float* srow = s + r * W_IN + 2 * tid;
            const ull A = *reinterpret_cast<const ull*>(srow);      // (i0,i1)
            const ull B = *reinterpret_cast<const ull*>(srow + 2);  // (i2,i3)
            const ull M = midpair(A, B);                            // (i1,i2)

#pragma unroll
            for (int ky = 0; ky < 3; ++ky) {
                const int o = r - ky;
                if (o >= 0 && o < TY) {
                    fma2(acc[o], wv[ky * 3 + 0], A);
                    fma2(acc[o], wv[ky * 3 + 1], M);
                    fma2(acc[o], wv[ky * 3 + 2], B);
                }
            }
        }

        float* op = out + (size_t)plane * (H_OUT * W_OUT)
                        + (size_t)iy0 * W_OUT + 2 * tid;
#pragma unroll
        for (int o = 0; o < TY; ++o)
            *reinterpret_cast<ull*>(op + (size_t)o * W_OUT) = acc[o];
    }
}

// ---- launch -----------------------------------------------------------------

extern "C" void kernel_launch(void* const* d_in, const int* in_sizes, int n_in,
                              void* d_out, int out_size)
{
    const float* x   = (const float*)d_in[0];   // (16, 64, 512, 512) fp32
    const float* w   = (const float*)d_in[1];   // (64, 3, 3) fp32
    float*       out = (float*)d_out;           // (16, 64, 510, 510) fp32

    dim3 grid(H_OUT / TY, 16 * C_CH);           // (51, 1024)
    dim3 block(NTHR);
    dwconv3x3_cpasync_kernel<<<grid, block>>>(x, w, out);
}